// round 2
// baseline (speedup 1.0000x reference)
#include <cuda_runtime.h>
#include <cstdint>

// ---------------- problem constants ----------------
#define IN_CH   32
#define OUT_CH  64
#define KDIM    2
#define KSZ     5            // kernel size per dim
#define KTOT    25           // 5*5
#define MAX_N   50016

// ---------------- scratch (device globals; no allocation allowed) ----------------
__device__ float g_acc[(size_t)MAX_N * 800];   // (N, 25, 32) accumulator, ~160 MB
__device__ int   g_deg[MAX_N];
__device__ float g_invdeg[MAX_N];

// ---------------- f32x2 helpers (Blackwell packed fp32) ----------------
// NOTE: packed-f32x2 ops require .b64 (untyped) registers -> "l" constraint.
__device__ __forceinline__ unsigned long long pack_f32x2(float lo, float hi) {
    unsigned long long d;
    asm("mov.b64 %0, {%1, %2};" : "=l"(d) : "f"(lo), "f"(hi));
    return d;
}
__device__ __forceinline__ void fma_f32x2(unsigned long long& c,
                                          unsigned long long a,
                                          unsigned long long b) {
    asm("fma.rn.f32x2 %0, %1, %2, %3;" : "=l"(c) : "l"(a), "l"(b), "l"(c));
}
__device__ __forceinline__ void unpack_f32x2(unsigned long long d, float& lo, float& hi) {
    asm("mov.b64 {%0, %1}, %2;" : "=f"(lo), "=f"(hi) : "l"(d));
}

// ---------------- kernel 1: zero scratch ----------------
__global__ void zero_kernel(size_t acc4, int N) {
    size_t stride = (size_t)gridDim.x * blockDim.x;
    size_t i = (size_t)blockIdx.x * blockDim.x + threadIdx.x;
    float4 z = make_float4(0.f, 0.f, 0.f, 0.f);
    float4* a4 = reinterpret_cast<float4*>(g_acc);
    for (size_t j = i; j < acc4; j += stride) a4[j] = z;
    for (size_t j = i; j < (size_t)N; j += stride) g_deg[j] = 0;
}

// ---------------- kernel 2: edge scatter (warp per edge) ----------------
// lane = 8*corner + channel_quad. One RED.128 per lane (vector atomic).
__global__ void scatter_kernel(const float* __restrict__ x,
                               const float* __restrict__ pseudo,
                               const int* __restrict__ ei,
                               int E) {
    int e = blockIdx.x * 8 + (threadIdx.x >> 5);
    if (e >= E) return;
    int lane = threadIdx.x & 31;

    int row = ei[e];
    int col = ei[E + e];
    float v0 = pseudo[2 * e]     * 4.0f;   // (ks - open) = 4
    float v1 = pseudo[2 * e + 1] * 4.0f;
    float b0f = floorf(v0), b1f = floorf(v1);
    float f0 = v0 - b0f, f1 = v1 - b1f;
    int i0 = (int)b0f, i1 = (int)b1f;

    int s   = lane >> 3;        // corner 0..3
    int c4  = lane & 7;         // channel quad 0..7
    int bit0 = s >> 1;          // dim-0 bit (matches meshgrid 'ij')
    int bit1 = s & 1;           // dim-1 bit
    int j0 = min(i0 + bit0, KSZ - 1);
    int j1 = min(i1 + bit1, KSZ - 1);
    int wi = j0 + KSZ * j1;
    float basis = (bit0 ? f0 : 1.0f - f0) * (bit1 ? f1 : 1.0f - f1);

    float4 xv = reinterpret_cast<const float4*>(x)[(size_t)col * 8 + c4];

    float* dst = g_acc + ((size_t)row * 800 + wi * 32 + c4 * 4);
    asm volatile("red.relaxed.gpu.global.add.v4.f32 [%0], {%1,%2,%3,%4};"
                 :: "l"(dst),
                    "f"(basis * xv.x), "f"(basis * xv.y),
                    "f"(basis * xv.z), "f"(basis * xv.w)
                 : "memory");

    if (lane == 0) atomicAdd(&g_deg[row], 1);
}

// ---------------- kernel 3: inverse degree ----------------
__global__ void invdeg_kernel(int N) {
    int n = blockIdx.x * 256 + threadIdx.x;
    if (n < N) g_invdeg[n] = 1.0f / (float)max(g_deg[n], 1);
}

// ---------------- kernel 4: fused GEMM  out = A(50000x832) @ W(832x64) + bias ----
// A rows 0..799  = acc * invdeg (per node), rows 800..831 = x (root term).
// Tile: BM=128 nodes x BN=64 outs, 256 threads, thread tile 4 rows x 8 cols.
// Accumulation in packed f32x2 pairs (cols n, n+1), B pairs read as 8B LDS.
#define BM 128
#define BK 32
#define AS_STRIDE 36   // BK+4, keeps 16B alignment, conflict-free A reads

__global__ __launch_bounds__(256) void gemm_kernel(const float* __restrict__ x,
                                                   const float* __restrict__ weight,
                                                   const float* __restrict__ bias,
                                                   float* __restrict__ out,
                                                   int N) {
    __shared__ float as[BM * AS_STRIDE];
    __shared__ float bs[BK * OUT_CH];

    int tid = threadIdx.x;
    int tx = tid & 7;      // col group: cols tx*8 .. tx*8+7
    int ty = tid >> 3;     // 0..31 ; owns rows ty + 32*r, r=0..3
    int n0 = blockIdx.x * BM;

    unsigned long long acc[4][4];
#pragma unroll
    for (int r = 0; r < 4; ++r)
#pragma unroll
        for (int j = 0; j < 4; ++j) acc[r][j] = pack_f32x2(0.f, 0.f);

    const int a_k4  = tid & 7;     // float4 index in k (0..7)
    const int a_row = tid >> 3;    // 0..31 (+32*p)
    const int b_c4  = tid & 15;    // float4 index in cols
    const int b_r   = tid >> 4;    // 0..15 (+16*p)

    for (int kt = 0; kt < 26; ++kt) {
        int kk0 = kt * BK;
        // ---- load A tile (128 x 32) ----
        if (kt < 25) {
#pragma unroll
            for (int p = 0; p < 4; ++p) {
                int m = a_row + 32 * p;
                int n = n0 + m;
                float4 v = make_float4(0.f, 0.f, 0.f, 0.f);
                float inv = 0.f;
                if (n < N) {
                    v = *reinterpret_cast<const float4*>(
                        &g_acc[(size_t)n * 800 + kk0 + a_k4 * 4]);
                    inv = g_invdeg[n];
                }
                v.x *= inv; v.y *= inv; v.z *= inv; v.w *= inv;
                *reinterpret_cast<float4*>(&as[m * AS_STRIDE + a_k4 * 4]) = v;
            }
        } else {  // root term: A = x (no invdeg)
#pragma unroll
            for (int p = 0; p < 4; ++p) {
                int m = a_row + 32 * p;
                int n = n0 + m;
                float4 v = make_float4(0.f, 0.f, 0.f, 0.f);
                if (n < N)
                    v = reinterpret_cast<const float4*>(x)[(size_t)n * 8 + a_k4];
                *reinterpret_cast<float4*>(&as[m * AS_STRIDE + a_k4 * 4]) = v;
            }
        }
        // ---- load B tile (32 x 64) ----
#pragma unroll
        for (int p = 0; p < 2; ++p) {
            int kr = b_r + 16 * p;
            float4 v = *reinterpret_cast<const float4*>(
                &weight[(size_t)(kk0 + kr) * OUT_CH + b_c4 * 4]);
            *reinterpret_cast<float4*>(&bs[kr * OUT_CH + b_c4 * 4]) = v;
        }
        __syncthreads();

        // ---- compute ----
#pragma unroll
        for (int k = 0; k < BK; ++k) {
            unsigned long long bd[4];
#pragma unroll
            for (int j = 0; j < 4; ++j)
                bd[j] = *reinterpret_cast<const unsigned long long*>(
                    &bs[k * OUT_CH + tx * 8 + j * 2]);
#pragma unroll
            for (int r = 0; r < 4; ++r) {
                float a = as[(ty + 32 * r) * AS_STRIDE + k];
                unsigned long long ap = pack_f32x2(a, a);
#pragma unroll
                for (int j = 0; j < 4; ++j) fma_f32x2(acc[r][j], ap, bd[j]);
            }
        }
        __syncthreads();
    }

    // ---- epilogue: + bias, store ----
    float bv[8];
#pragma unroll
    for (int j = 0; j < 8; ++j) bv[j] = bias[tx * 8 + j];

#pragma unroll
    for (int r = 0; r < 4; ++r) {
        int n = n0 + ty + 32 * r;
        if (n >= N) continue;
        float o[8];
#pragma unroll
        for (int j = 0; j < 4; ++j) unpack_f32x2(acc[r][j], o[2 * j], o[2 * j + 1]);
#pragma unroll
        for (int j = 0; j < 8; ++j) o[j] += bv[j];
        float* op = &out[(size_t)n * OUT_CH + tx * 8];
        *reinterpret_cast<float4*>(op)     = make_float4(o[0], o[1], o[2], o[3]);
        *reinterpret_cast<float4*>(op + 4) = make_float4(o[4], o[5], o[6], o[7]);
    }
}

// ---------------- launch ----------------
extern "C" void kernel_launch(void* const* d_in, const int* in_sizes, int n_in,
                              void* d_out, int out_size) {
    const float* x      = (const float*)d_in[0];
    const float* pseudo = (const float*)d_in[1];
    const int*   ei     = (const int*)  d_in[2];
    const float* weight = (const float*)d_in[3];
    const float* bias   = (const float*)d_in[4];
    float* out = (float*)d_out;

    int N = in_sizes[0] / IN_CH;
    int E = in_sizes[1] / KDIM;

    size_t acc4 = (size_t)N * 800 / 4;
    zero_kernel<<<4096, 256>>>(acc4, N);
    scatter_kernel<<<(E + 7) / 8, 256>>>(x, pseudo, ei, E);
    invdeg_kernel<<<(N + 255) / 256, 256>>>(N);
    gemm_kernel<<<(N + BM - 1) / BM, 256>>>(x, weight, bias, out, N);
}